// round 1
// baseline (speedup 1.0000x reference)
#include <cuda_runtime.h>
#include <math.h>

#define NA   4096
#define NE   131072
#define DMSG 128
#define TPIN 1152

// ---------------- scratch (static device globals; no allocs) ----------------
__device__ float g_sh[NE * 9];
__device__ float g_h1[(size_t)NE * 64];
__device__ float g_rad[(size_t)NE * 128];
__device__ int   g_hist[NA];
__device__ int   g_off[NA];
__device__ int   g_cur[NA];
__device__ int   g_elist[NE];
__device__ float g_A[(size_t)NA * TPIN];
__device__ float g_comb[NA * 128];
__device__ float g_hid[NA * 128];
__device__ float g_upd[NA * 128];
__device__ float g_qkv[NA * 384];
__device__ float g_att[NA * 128];
__device__ float g_t1[NA * 128];
__device__ float g_t2[NA * 128];
__device__ float g_mix[NA * 128];

// ---------------- edge kernel: sh + rbf + radial layer 1 ----------------
// one warp per edge; lane computes h1[lane], h1[lane+32]
__global__ void edge_rbf_kernel(const float* __restrict__ ev,
                                const float* __restrict__ el,
                                const float* __restrict__ W1,
                                const float* __restrict__ b1) {
    int warp = threadIdx.x >> 5, lane = threadIdx.x & 31;
    int e = blockIdx.x * 8 + warp;
    if (e >= NE) return;
    float vx = ev[e * 3 + 0], vy = ev[e * 3 + 1], vz = ev[e * 3 + 2];
    float l = el[e];
    float r = sqrtf(vx * vx + vy * vy + vz * vz) + 1e-8f;
    float x = vx / r, y = vy / r, z = vz / r;
    if (lane < 9) {
        float s;
        switch (lane) {
            case 0: s = 1.f; break;
            case 1: s = y; break;
            case 2: s = z; break;
            case 3: s = x; break;
            case 4: s = 3.f * z * z - 1.f; break;
            case 5: s = x * z; break;
            case 6: s = y * z; break;
            case 7: s = x * y; break;
            default: s = x * x - y * y; break;
        }
        g_sh[e * 9 + lane] = s;
    }
    const float PIC = 3.14159265358979323846f / 6.0f;
    float env = 0.5f * (cosf(l * PIC) + 1.f) * (l < 6.0f ? 1.f : 0.f);
    float rb[8];
#pragma unroll
    for (int b = 0; b < 8; b++) rb[b] = sinf(l * (float)(b + 1) * PIC) / l * env;
#pragma unroll
    for (int h = 0; h < 2; h++) {
        int o = lane + h * 32;
        float acc = b1[o];
#pragma unroll
        for (int b = 0; b < 8; b++) acc += rb[b] * W1[b * 64 + o];
        acc = acc / (1.f + __expf(-acc));            // silu
        g_h1[(size_t)e * 64 + o] = acc;
    }
}

// ---------------- generic tiled fp32 GEMM: C = act(A[MxK] @ W[KxN] + b) ----
// BM=64, BN=64, BK=32, 256 threads, 4x4 micro-tile. act: 0 none, 1 silu, 2 sigmoid
__global__ void gemm_kernel(const float* __restrict__ A, const float* __restrict__ W,
                            const float* __restrict__ bias, float* __restrict__ C,
                            int M, int N, int K, int act) {
    __shared__ float As[32 * 65];
    __shared__ float Bs[32 * 64];
    int tx = threadIdx.x & 15, ty = threadIdx.x >> 4;
    int m0 = blockIdx.x * 64, n0 = blockIdx.y * 64;
    float acc[4][4] = {};
    for (int k0 = 0; k0 < K; k0 += 32) {
#pragma unroll
        for (int i = 0; i < 8; i++) {
            int l = threadIdx.x + i * 256;
            int m = l >> 5, k = l & 31;
            As[k * 65 + m] = A[(size_t)(m0 + m) * K + k0 + k];
        }
#pragma unroll
        for (int i = 0; i < 8; i++) {
            int l = threadIdx.x + i * 256;
            int k = l >> 6, n = l & 63;
            Bs[k * 64 + n] = W[(size_t)(k0 + k) * N + n0 + n];
        }
        __syncthreads();
#pragma unroll
        for (int k = 0; k < 32; k++) {
            float a[4], b[4];
#pragma unroll
            for (int i = 0; i < 4; i++) a[i] = As[k * 65 + ty * 4 + i];
#pragma unroll
            for (int j = 0; j < 4; j++) b[j] = Bs[k * 64 + tx * 4 + j];
#pragma unroll
            for (int i = 0; i < 4; i++)
#pragma unroll
                for (int j = 0; j < 4; j++) acc[i][j] += a[i] * b[j];
        }
        __syncthreads();
    }
#pragma unroll
    for (int i = 0; i < 4; i++) {
        int m = m0 + ty * 4 + i;
#pragma unroll
        for (int j = 0; j < 4; j++) {
            int n = n0 + tx * 4 + j;
            float v = acc[i][j] + bias[n];
            if (act == 1) v = v / (1.f + __expf(-v));
            else if (act == 2) v = 1.f / (1.f + __expf(-v));
            C[(size_t)m * N + n] = v;
        }
    }
}

// ---------------- CSR build ----------------
__global__ void zero_hist_kernel() {
    int i = blockIdx.x * blockDim.x + threadIdx.x;
    if (i < NA) g_hist[i] = 0;
}
__global__ void hist_kernel(const int* __restrict__ ei) {
    for (int e = blockIdx.x * blockDim.x + threadIdx.x; e < NE; e += gridDim.x * blockDim.x)
        atomicAdd(&g_hist[ei[NE + e]], 1);
}
__global__ void scan_kernel() {   // 1 block, 1024 threads, 4 elems each
    __shared__ int s[1024];
    int t = threadIdx.x;
    int v0 = g_hist[t * 4], v1 = g_hist[t * 4 + 1], v2 = g_hist[t * 4 + 2], v3 = g_hist[t * 4 + 3];
    int sum = v0 + v1 + v2 + v3;
    s[t] = sum;
    __syncthreads();
    for (int d = 1; d < 1024; d <<= 1) {
        int add = (t >= d) ? s[t - d] : 0;
        __syncthreads();
        s[t] += add;
        __syncthreads();
    }
    int base = s[t] - sum;
    g_off[t * 4 + 0] = base;                 g_cur[t * 4 + 0] = base;
    g_off[t * 4 + 1] = base + v0;            g_cur[t * 4 + 1] = base + v0;
    g_off[t * 4 + 2] = base + v0 + v1;       g_cur[t * 4 + 2] = base + v0 + v1;
    g_off[t * 4 + 3] = base + v0 + v1 + v2;  g_cur[t * 4 + 3] = base + v0 + v1 + v2;
}
__global__ void scatter_kernel(const int* __restrict__ ei) {
    for (int e = blockIdx.x * blockDim.x + threadIdx.x; e < NE; e += gridDim.x * blockDim.x) {
        int d = ei[NE + e];
        int p = atomicAdd(&g_cur[d], 1);
        g_elist[p] = e;
    }
}

// ---------------- per-node rank-1 aggregation: A_n = sum radial ⊗ sh -------
// one block per node, thread = channel c; output written in W_tp row layout.
__global__ void aggregate_kernel() {
    int n = blockIdx.x;
    int c = threadIdx.x;  // 128 threads
    int start = g_off[n], cnt = g_hist[n];
    __shared__ int   eid[32];
    __shared__ float shs[32 * 9];
    float acc[9] = {};
    for (int base = 0; base < cnt; base += 32) {
        int m = min(32, cnt - base);
        if (c < m) eid[c] = g_elist[start + base + c];
        __syncthreads();
        for (int j = c; j < m * 9; j += 128) shs[j] = g_sh[(size_t)eid[j / 9] * 9 + j % 9];
        __syncthreads();
        for (int i = 0; i < m; i++) {
            float rv = g_rad[(size_t)eid[i] * 128 + c];
#pragma unroll
            for (int s = 0; s < 9; s++) acc[s] += rv * shs[i * 9 + s];
        }
        __syncthreads();
    }
    size_t b = (size_t)n * TPIN;
    g_A[b + c] = acc[0];
#pragma unroll
    for (int s = 1; s < 4; s++) g_A[b + 128 + c * 3 + (s - 1)] = acc[s];
#pragma unroll
    for (int s = 4; s < 9; s++) g_A[b + 512 + c * 5 + (s - 4)] = acc[s];
}

// ---------------- aggregated @ W_tp[:, :64] + deg*b_tp -> combined[:,64:] --
__global__ void agg_gemm_kernel(const float* __restrict__ Wtp, const float* __restrict__ btp) {
    __shared__ float As[32 * 65];
    __shared__ float Bs[32 * 64];
    int tx = threadIdx.x & 15, ty = threadIdx.x >> 4;
    int m0 = blockIdx.x * 64;
    float acc[4][4] = {};
    for (int k0 = 0; k0 < TPIN; k0 += 32) {
#pragma unroll
        for (int i = 0; i < 8; i++) {
            int l = threadIdx.x + i * 256;
            int m = l >> 5, k = l & 31;
            As[k * 65 + m] = g_A[(size_t)(m0 + m) * TPIN + k0 + k];
        }
#pragma unroll
        for (int i = 0; i < 8; i++) {
            int l = threadIdx.x + i * 256;
            int k = l >> 6, n = l & 63;
            Bs[k * 64 + n] = Wtp[(k0 + k) * 128 + n];
        }
        __syncthreads();
#pragma unroll
        for (int k = 0; k < 32; k++) {
            float a[4], b[4];
#pragma unroll
            for (int i = 0; i < 4; i++) a[i] = As[k * 65 + ty * 4 + i];
#pragma unroll
            for (int j = 0; j < 4; j++) b[j] = Bs[k * 64 + tx * 4 + j];
#pragma unroll
            for (int i = 0; i < 4; i++)
#pragma unroll
                for (int j = 0; j < 4; j++) acc[i][j] += a[i] * b[j];
        }
        __syncthreads();
    }
#pragma unroll
    for (int i = 0; i < 4; i++) {
        int m = m0 + ty * 4 + i;
        float deg = (float)g_hist[m];
#pragma unroll
        for (int j = 0; j < 4; j++) {
            int n = tx * 4 + j;
            g_comb[m * 128 + 64 + n] = acc[i][j] + btp[n] * deg;
        }
    }
}

__global__ void embed_kernel(const int* __restrict__ an, const float* __restrict__ emb) {
    int i = blockIdx.x * blockDim.x + threadIdx.x;
    if (i < NA * 64) {
        int n = i >> 6, j = i & 63;
        g_comb[n * 128 + j] = emb[an[n] * 64 + j];
    }
}

// ---------------- dense attention, online softmax ----------------
// block = 64 queries x 1 head, 8 warps, warp handles 8 queries; lane = headdim/key
__global__ void attn_kernel() {
    __shared__ float Ks[32][33];  // [d][key]
    __shared__ float Vs[32][33];  // [key][d]
    int tid = threadIdx.x, lane = tid & 31, w = tid >> 5;
    int h = blockIdx.y;
    int q0 = blockIdx.x * 64 + w * 8;
    const float sc = 0.17677669529663687f;  // 1/sqrt(32)
    float q[8], O[8], Mx[8], L[8];
#pragma unroll
    for (int i = 0; i < 8; i++) {
        q[i] = g_qkv[(size_t)(q0 + i) * 384 + h * 32 + lane] * sc;
        O[i] = 0.f; Mx[i] = -1e30f; L[i] = 0.f;
    }
    for (int m0 = 0; m0 < NA; m0 += 32) {
#pragma unroll
        for (int i = 0; i < 4; i++) {
            int l = tid + i * 256;
            int key = l >> 5, d = l & 31;
            Ks[d][key] = g_qkv[(size_t)(m0 + key) * 384 + 128 + h * 32 + d];
            Vs[key][d] = g_qkv[(size_t)(m0 + key) * 384 + 256 + h * 32 + d];
        }
        __syncthreads();
        float kreg[32], vreg[32];
#pragma unroll
        for (int d = 0; d < 32; d++) kreg[d] = Ks[d][lane];
#pragma unroll
        for (int j = 0; j < 32; j++) vreg[j] = Vs[j][lane];
#pragma unroll
        for (int i = 0; i < 8; i++) {
            float s = 0.f;
#pragma unroll
            for (int d = 0; d < 32; d++)
                s += __shfl_sync(0xffffffffu, q[i], d) * kreg[d];
            float rmax = s;
#pragma unroll
            for (int o = 16; o > 0; o >>= 1)
                rmax = fmaxf(rmax, __shfl_xor_sync(0xffffffffu, rmax, o));
            float mnew = fmaxf(Mx[i], rmax);
            float p = __expf(s - mnew);
            float ps = p;
#pragma unroll
            for (int o = 16; o > 0; o >>= 1)
                ps += __shfl_xor_sync(0xffffffffu, ps, o);
            float scal = __expf(Mx[i] - mnew);
            float o_ = O[i] * scal;
            L[i] = L[i] * scal + ps;
            Mx[i] = mnew;
#pragma unroll
            for (int j = 0; j < 32; j++)
                o_ += __shfl_sync(0xffffffffu, p, j) * vreg[j];
            O[i] = o_;
        }
        __syncthreads();
    }
#pragma unroll
    for (int i = 0; i < 8; i++)
        g_att[(size_t)(q0 + i) * 128 + h * 32 + lane] = O[i] / L[i];
}

__global__ void mix_kernel() {
    int i = blockIdx.x * blockDim.x + threadIdx.x;
    if (i < NA * 128) {
        float g = g_t2[i];
        g_mix[i] = g * g_t1[i] + (1.f - g) * g_upd[i];
    }
}

// ---------------- launch ----------------
extern "C" void kernel_launch(void* const* d_in, const int* in_sizes, int n_in,
                              void* d_out, int out_size) {
    const int*   an    = (const int*)d_in[0];
    const int*   ei    = (const int*)d_in[2];
    const float* ev    = (const float*)d_in[3];
    const float* el    = (const float*)d_in[4];
    const float* emb   = (const float*)d_in[5];
    const float* W_r1  = (const float*)d_in[6];  const float* b_r1 = (const float*)d_in[7];
    const float* W_r2  = (const float*)d_in[8];  const float* b_r2 = (const float*)d_in[9];
    const float* W_tp  = (const float*)d_in[10]; const float* b_tp = (const float*)d_in[11];
    const float* W_m1  = (const float*)d_in[12]; const float* b_m1 = (const float*)d_in[13];
    const float* W_m2  = (const float*)d_in[14]; const float* b_m2 = (const float*)d_in[15];
    const float* W_qkv = (const float*)d_in[16]; const float* b_qkv= (const float*)d_in[17];
    const float* W_ao  = (const float*)d_in[18]; const float* b_ao = (const float*)d_in[19];
    const float* W_g   = (const float*)d_in[20]; const float* b_g  = (const float*)d_in[21];
    const float* W_o   = (const float*)d_in[22]; const float* b_o  = (const float*)d_in[23];
    float* out = (float*)d_out;

    float *p_h1, *p_rad, *p_comb, *p_hid, *p_upd, *p_qkv, *p_att, *p_t1, *p_t2, *p_mix;
    cudaGetSymbolAddress((void**)&p_h1,  g_h1);
    cudaGetSymbolAddress((void**)&p_rad, g_rad);
    cudaGetSymbolAddress((void**)&p_comb,g_comb);
    cudaGetSymbolAddress((void**)&p_hid, g_hid);
    cudaGetSymbolAddress((void**)&p_upd, g_upd);
    cudaGetSymbolAddress((void**)&p_qkv, g_qkv);
    cudaGetSymbolAddress((void**)&p_att, g_att);
    cudaGetSymbolAddress((void**)&p_t1,  g_t1);
    cudaGetSymbolAddress((void**)&p_t2,  g_t2);
    cudaGetSymbolAddress((void**)&p_mix, g_mix);

    zero_hist_kernel<<<16, 256>>>();
    edge_rbf_kernel<<<NE / 8, 256>>>(ev, el, W_r1, b_r1);
    gemm_kernel<<<dim3(NE / 64, 2), 256>>>(p_h1, W_r2, b_r2, p_rad, NE, 128, 64, 1);
    hist_kernel<<<512, 256>>>(ei);
    scan_kernel<<<1, 1024>>>();
    scatter_kernel<<<512, 256>>>(ei);
    aggregate_kernel<<<NA, 128>>>();
    agg_gemm_kernel<<<NA / 64, 256>>>(W_tp, b_tp);
    embed_kernel<<<NA * 64 / 256, 256>>>(an, emb);
    gemm_kernel<<<dim3(NA / 64, 2), 256>>>(p_comb, W_m1, b_m1, p_hid, NA, 128, 128, 1);
    gemm_kernel<<<dim3(NA / 64, 2), 256>>>(p_hid, W_m2, b_m2, p_upd, NA, 128, 128, 0);
    gemm_kernel<<<dim3(NA / 64, 6), 256>>>(p_upd, W_qkv, b_qkv, p_qkv, NA, 384, 128, 0);
    attn_kernel<<<dim3(NA / 64, 4), 256>>>();
    gemm_kernel<<<dim3(NA / 64, 2), 256>>>(p_att, W_ao, b_ao, p_t1, NA, 128, 128, 0);
    gemm_kernel<<<dim3(NA / 64, 2), 256>>>(p_upd, W_g, b_g, p_t2, NA, 128, 128, 2);
    mix_kernel<<<NA * 128 / 256, 256>>>();
    gemm_kernel<<<dim3(NA / 64, 2), 256>>>(p_mix, W_o, b_o, out, NA, 128, 128, 0);
}

// round 3
// speedup vs baseline: 1.0807x; 1.0807x over previous
#include <cuda_runtime.h>
#include <math.h>

#define NA   4096
#define NE   131072
#define TPIN 1152

typedef unsigned long long u64t;

__device__ __forceinline__ u64t pk2(float a, float b) {
    u64t r; asm("mov.b64 %0,{%1,%2};" : "=l"(r) : "f"(a), "f"(b)); return r;
}
__device__ __forceinline__ void upk2(u64t v, float& a, float& b) {
    asm("mov.b64 {%0,%1},%2;" : "=f"(a), "=f"(b) : "l"(v));
}
__device__ __forceinline__ u64t ffma2(u64t a, u64t b, u64t c) {
    u64t d; asm("fma.rn.f32x2 %0,%1,%2,%3;" : "=l"(d) : "l"(a), "l"(b), "l"(c)); return d;
}
__device__ __forceinline__ u64t fmul2(u64t a, u64t b) {
    u64t d; asm("mul.rn.f32x2 %0,%1,%2;" : "=l"(d) : "l"(a), "l"(b)); return d;
}

// ---------------- scratch ----------------
__device__ float g_sh[NE * 9];
__device__ float g_rad[(size_t)NE * 128];
__device__ int   g_hist[NA];
__device__ int   g_off[NA];
__device__ int   g_cur[NA];
__device__ int   g_elist[NE];
__device__ float g_A[(size_t)NA * TPIN];
__device__ float g_comb[NA * 128];
__device__ float g_hid[NA * 128];
__device__ float g_upd[NA * 128];
__device__ float g_qkv[NA * 384];
__device__ float g_att[NA * 128];
__device__ float g_mix[NA * 128];

// ---------------- fused edge kernel: sh + rbf + radial L1 + radial L2 -------
// 256 threads (8 warps), grid 512; warp handles one edge per iteration.
__global__ __launch_bounds__(256) void edge_fused_kernel(
        const float* __restrict__ ev, const float* __restrict__ el,
        const float* __restrict__ W1, const float* __restrict__ b1,
        const float* __restrict__ W2, const float* __restrict__ b2) {
    __shared__ float sW1[8 * 64];
    __shared__ float sb1[64];
    __shared__ __align__(16) float sW2[64 * 128];
    __shared__ float sb2[128];
    for (int i = threadIdx.x; i < 512;  i += 256) sW1[i] = W1[i];
    for (int i = threadIdx.x; i < 64;   i += 256) sb1[i] = b1[i];
    for (int i = threadIdx.x; i < 8192; i += 256) sW2[i] = W2[i];
    for (int i = threadIdx.x; i < 128;  i += 256) sb2[i] = b2[i];
    __syncthreads();

    int warp = threadIdx.x >> 5, lane = threadIdx.x & 31;
    const float PIC = 3.14159265358979323846f / 6.0f;
    for (int it = 0; it < NE / 4096; it++) {
        int e = blockIdx.x * 8 + warp + it * 4096;
        float vx = ev[e * 3 + 0], vy = ev[e * 3 + 1], vz = ev[e * 3 + 2];
        float l = el[e];
        float r = sqrtf(vx * vx + vy * vy + vz * vz) + 1e-8f;
        float x = vx / r, y = vy / r, z = vz / r;
        if (lane < 9) {
            float s;
            switch (lane) {
                case 0: s = 1.f; break;
                case 1: s = y; break;
                case 2: s = z; break;
                case 3: s = x; break;
                case 4: s = 3.f * z * z - 1.f; break;
                case 5: s = x * z; break;
                case 6: s = y * z; break;
                case 7: s = x * y; break;
                default: s = x * x - y * y; break;
            }
            g_sh[e * 9 + lane] = s;
        }
        float env = 0.5f * (__cosf(l * PIC) + 1.f) * (l < 6.0f ? 1.f : 0.f);
        float inv_l_env = env / l;
        float rb[8];
#pragma unroll
        for (int b = 0; b < 8; b++) rb[b] = __sinf(l * (float)(b + 1) * PIC) * inv_l_env;
        // layer 1: lane owns outputs lane and lane+32
        float h1a = sb1[lane], h1b = sb1[lane + 32];
#pragma unroll
        for (int b = 0; b < 8; b++) {
            h1a += rb[b] * sW1[b * 64 + lane];
            h1b += rb[b] * sW1[b * 64 + lane + 32];
        }
        h1a = h1a / (1.f + __expf(-h1a));
        h1b = h1b / (1.f + __expf(-h1b));
        // layer 2: lane owns outputs lane*4 .. lane*4+3 (packed f32x2)
        u64t acc0 = pk2(sb2[lane * 4 + 0], sb2[lane * 4 + 1]);
        u64t acc1 = pk2(sb2[lane * 4 + 2], sb2[lane * 4 + 3]);
#pragma unroll
        for (int k = 0; k < 64; k++) {
            float hk = (k < 32) ? __shfl_sync(0xffffffffu, h1a, k)
                                : __shfl_sync(0xffffffffu, h1b, k - 32);
            u64t hk2 = pk2(hk, hk);
            ulonglong2 w = *(const ulonglong2*)&sW2[k * 128 + lane * 4];
            acc0 = ffma2(hk2, w.x, acc0);
            acc1 = ffma2(hk2, w.y, acc1);
        }
        float o0, o1, o2, o3;
        upk2(acc0, o0, o1); upk2(acc1, o2, o3);
        o0 = o0 / (1.f + __expf(-o0));
        o1 = o1 / (1.f + __expf(-o1));
        o2 = o2 / (1.f + __expf(-o2));
        o3 = o3 / (1.f + __expf(-o3));
        *(float4*)&g_rad[(size_t)e * 128 + lane * 4] = make_float4(o0, o1, o2, o3);
    }
}

// ---------------- generic tiled fp32 GEMM ----------------
__global__ void gemm_kernel(const float* __restrict__ A, const float* __restrict__ W,
                            const float* __restrict__ bias, float* __restrict__ C,
                            int M, int N, int K, int act) {
    __shared__ float As[32 * 65];
    __shared__ float Bs[32 * 64];
    int tx = threadIdx.x & 15, ty = threadIdx.x >> 4;
    int m0 = blockIdx.x * 64, n0 = blockIdx.y * 64;
    float acc[4][4] = {};
    for (int k0 = 0; k0 < K; k0 += 32) {
#pragma unroll
        for (int i = 0; i < 8; i++) {
            int l = threadIdx.x + i * 256;
            int m = l >> 5, k = l & 31;
            As[k * 65 + m] = A[(size_t)(m0 + m) * K + k0 + k];
        }
#pragma unroll
        for (int i = 0; i < 8; i++) {
            int l = threadIdx.x + i * 256;
            int k = l >> 6, n = l & 63;
            Bs[k * 64 + n] = W[(size_t)(k0 + k) * N + n0 + n];
        }
        __syncthreads();
#pragma unroll
        for (int k = 0; k < 32; k++) {
            float a[4], b[4];
#pragma unroll
            for (int i = 0; i < 4; i++) a[i] = As[k * 65 + ty * 4 + i];
#pragma unroll
            for (int j = 0; j < 4; j++) b[j] = Bs[k * 64 + tx * 4 + j];
#pragma unroll
            for (int i = 0; i < 4; i++)
#pragma unroll
                for (int j = 0; j < 4; j++) acc[i][j] += a[i] * b[j];
        }
        __syncthreads();
    }
#pragma unroll
    for (int i = 0; i < 4; i++) {
        int m = m0 + ty * 4 + i;
#pragma unroll
        for (int j = 0; j < 4; j++) {
            int n = n0 + tx * 4 + j;
            float v = acc[i][j] + bias[n];
            if (act == 1) v = v / (1.f + __expf(-v));
            else if (act == 2) v = 1.f / (1.f + __expf(-v));
            C[(size_t)m * N + n] = v;
        }
    }
}

// ---------------- CSR build ----------------
__global__ void zero_hist_kernel() {
    int i = blockIdx.x * blockDim.x + threadIdx.x;
    if (i < NA) g_hist[i] = 0;
}
__global__ void hist_kernel(const int* __restrict__ ei) {
    for (int e = blockIdx.x * blockDim.x + threadIdx.x; e < NE; e += gridDim.x * blockDim.x)
        atomicAdd(&g_hist[ei[NE + e]], 1);
}
__global__ void scan_kernel() {
    __shared__ int s[1024];
    int t = threadIdx.x;
    int v0 = g_hist[t * 4], v1 = g_hist[t * 4 + 1], v2 = g_hist[t * 4 + 2], v3 = g_hist[t * 4 + 3];
    int sum = v0 + v1 + v2 + v3;
    s[t] = sum;
    __syncthreads();
    for (int d = 1; d < 1024; d <<= 1) {
        int add = (t >= d) ? s[t - d] : 0;
        __syncthreads();
        s[t] += add;
        __syncthreads();
    }
    int base = s[t] - sum;
    g_off[t * 4 + 0] = base;                 g_cur[t * 4 + 0] = base;
    g_off[t * 4 + 1] = base + v0;            g_cur[t * 4 + 1] = base + v0;
    g_off[t * 4 + 2] = base + v0 + v1;       g_cur[t * 4 + 2] = base + v0 + v1;
    g_off[t * 4 + 3] = base + v0 + v1 + v2;  g_cur[t * 4 + 3] = base + v0 + v1 + v2;
}
__global__ void scatter_kernel(const int* __restrict__ ei) {
    for (int e = blockIdx.x * blockDim.x + threadIdx.x; e < NE; e += gridDim.x * blockDim.x) {
        int d = ei[NE + e];
        int p = atomicAdd(&g_cur[d], 1);
        g_elist[p] = e;
    }
}

// ---------------- per-node rank-1 aggregation ----------------
__global__ void aggregate_kernel() {
    int n = blockIdx.x;
    int c = threadIdx.x;  // 128
    int start = g_off[n], cnt = g_hist[n];
    __shared__ int   eid[32];
    __shared__ float shs[32 * 9];
    float acc[9] = {};
    for (int base = 0; base < cnt; base += 32) {
        int m = min(32, cnt - base);
        if (c < m) eid[c] = g_elist[start + base + c];
        __syncthreads();
        for (int j = c; j < m * 9; j += 128) shs[j] = g_sh[(size_t)eid[j / 9] * 9 + j % 9];
        __syncthreads();
        for (int i = 0; i < m; i++) {
            float rv = g_rad[(size_t)eid[i] * 128 + c];
#pragma unroll
            for (int s = 0; s < 9; s++) acc[s] += rv * shs[i * 9 + s];
        }
        __syncthreads();
    }
    size_t b = (size_t)n * TPIN;
    g_A[b + c] = acc[0];
#pragma unroll
    for (int s = 1; s < 4; s++) g_A[b + 128 + c * 3 + (s - 1)] = acc[s];
#pragma unroll
    for (int s = 4; s < 9; s++) g_A[b + 512 + c * 5 + (s - 4)] = acc[s];
}

// ---------------- embed + bias*deg init of g_comb ----------------
__global__ void embed_kernel(const int* __restrict__ an, const float* __restrict__ emb,
                             const float* __restrict__ btp) {
    int i = blockIdx.x * blockDim.x + threadIdx.x;
    if (i < NA * 128) {
        int n = i >> 7, j = i & 127;
        g_comb[i] = (j < 64) ? emb[an[n] * 64 + j]
                             : btp[j - 64] * (float)g_hist[n];
    }
}

// ---------------- split-K GEMM: g_A @ W_tp[:, :64] -> atomicAdd g_comb[:,64:]
__global__ void agg_gemm_kernel(const float* __restrict__ Wtp) {
    __shared__ float As[32 * 65];
    __shared__ float Bs[32 * 64];
    int tx = threadIdx.x & 15, ty = threadIdx.x >> 4;
    int m0 = blockIdx.x * 64;
    int kb = blockIdx.y * 288;
    float acc[4][4] = {};
    for (int k0 = 0; k0 < 288; k0 += 32) {
#pragma unroll
        for (int i = 0; i < 8; i++) {
            int l = threadIdx.x + i * 256;
            int m = l >> 5, k = l & 31;
            As[k * 65 + m] = g_A[(size_t)(m0 + m) * TPIN + kb + k0 + k];
        }
#pragma unroll
        for (int i = 0; i < 8; i++) {
            int l = threadIdx.x + i * 256;
            int k = l >> 6, n = l & 63;
            Bs[k * 64 + n] = Wtp[(kb + k0 + k) * 128 + n];
        }
        __syncthreads();
#pragma unroll
        for (int k = 0; k < 32; k++) {
            float a[4], b[4];
#pragma unroll
            for (int i = 0; i < 4; i++) a[i] = As[k * 65 + ty * 4 + i];
#pragma unroll
            for (int j = 0; j < 4; j++) b[j] = Bs[k * 64 + tx * 4 + j];
#pragma unroll
            for (int i = 0; i < 4; i++)
#pragma unroll
                for (int j = 0; j < 4; j++) acc[i][j] += a[i] * b[j];
        }
        __syncthreads();
    }
#pragma unroll
    for (int i = 0; i < 4; i++) {
        int m = m0 + ty * 4 + i;
#pragma unroll
        for (int j = 0; j < 4; j++) {
            int n = tx * 4 + j;
            atomicAdd(&g_comb[m * 128 + 64 + n], acc[i][j]);
        }
    }
}

// ---------------- dense attention, online softmax, packed f32x2 ------------
// block = 64 queries (thread = query), grid (64, 4 heads)
__global__ __launch_bounds__(64) void attn_kernel() {
    __shared__ __align__(16) float Ks[32][32];
    __shared__ __align__(16) float Vs[32][32];
    int t = threadIdx.x;
    int h = blockIdx.y;
    int qi = blockIdx.x * 64 + t;
    const float sc = 0.17677669529663687f;  // 1/sqrt(32)
    u64t q2[16], O2[16];
    const float4* qp = (const float4*)&g_qkv[(size_t)qi * 384 + h * 32];
#pragma unroll
    for (int i = 0; i < 8; i++) {
        float4 v = qp[i];
        q2[2 * i]     = pk2(v.x * sc, v.y * sc);
        q2[2 * i + 1] = pk2(v.z * sc, v.w * sc);
    }
#pragma unroll
    for (int i = 0; i < 16; i++) O2[i] = 0ull;  // two packed 0.0f
    float M = -1e30f, L = 0.f;
    for (int m0 = 0; m0 < NA; m0 += 32) {
#pragma unroll
        for (int i = 0; i < 4; i++) {
            int u = t + i * 64;
            int j = u >> 3, dd = (u & 7) * 4;
            *(float4*)&Ks[j][dd] = *(const float4*)&g_qkv[(size_t)(m0 + j) * 384 + 128 + h * 32 + dd];
            *(float4*)&Vs[j][dd] = *(const float4*)&g_qkv[(size_t)(m0 + j) * 384 + 256 + h * 32 + dd];
        }
        __syncthreads();
        float s[32];
#pragma unroll
        for (int j = 0; j < 32; j++) {
            const ulonglong2* kp = (const ulonglong2*)&Ks[j][0];
            u64t a0 = 0ull, a1 = 0ull;
#pragma unroll
            for (int i = 0; i < 8; i++) {
                ulonglong2 kk = kp[i];
                a0 = ffma2(q2[2 * i], kk.x, a0);
                a1 = ffma2(q2[2 * i + 1], kk.y, a1);
            }
            float lo0, hi0, lo1, hi1;
            upk2(a0, lo0, hi0); upk2(a1, lo1, hi1);
            s[j] = (lo0 + hi0) + (lo1 + hi1);
        }
        float cm = s[0];
#pragma unroll
        for (int j = 1; j < 32; j++) cm = fmaxf(cm, s[j]);
        float Mn = fmaxf(M, cm);
        float scal = __expf(M - Mn);
        float ps = 0.f;
#pragma unroll
        for (int j = 0; j < 32; j++) { s[j] = __expf(s[j] - Mn); ps += s[j]; }
        L = L * scal + ps;
        M = Mn;
        u64t scal2 = pk2(scal, scal);
#pragma unroll
        for (int i = 0; i < 16; i++) O2[i] = fmul2(O2[i], scal2);
#pragma unroll
        for (int j = 0; j < 32; j++) {
            u64t pp = pk2(s[j], s[j]);
            const ulonglong2* vp = (const ulonglong2*)&Vs[j][0];
#pragma unroll
            for (int i = 0; i < 8; i++) {
                ulonglong2 vv = vp[i];
                O2[2 * i]     = ffma2(pp, vv.x, O2[2 * i]);
                O2[2 * i + 1] = ffma2(pp, vv.y, O2[2 * i + 1]);
            }
        }
        __syncthreads();
    }
    float inv = 1.f / L;
    float* op = &g_att[(size_t)qi * 128 + h * 32];
#pragma unroll
    for (int i = 0; i < 8; i++) {
        float a, b, c, d;
        upk2(O2[2 * i], a, b); upk2(O2[2 * i + 1], c, d);
        *(float4*)&op[i * 4] = make_float4(a * inv, b * inv, c * inv, d * inv);
    }
}

// ---------------- fused: t1 = att@Wao+bao; g = sig(upd@Wg+bg); mix ---------
__global__ void gemm_dual_kernel(const float* __restrict__ Wao, const float* __restrict__ bao,
                                 const float* __restrict__ Wg,  const float* __restrict__ bg) {
    __shared__ float As1[32 * 65];
    __shared__ float As2[32 * 65];
    __shared__ float Bs1[32 * 64];
    __shared__ float Bs2[32 * 64];
    int tx = threadIdx.x & 15, ty = threadIdx.x >> 4;
    int m0 = blockIdx.x * 64, n0 = blockIdx.y * 64;
    float acc1[4][4] = {}, acc2[4][4] = {};
    for (int k0 = 0; k0 < 128; k0 += 32) {
#pragma unroll
        for (int i = 0; i < 8; i++) {
            int l = threadIdx.x + i * 256;
            int m = l >> 5, k = l & 31;
            As1[k * 65 + m] = g_att[(size_t)(m0 + m) * 128 + k0 + k];
            As2[k * 65 + m] = g_upd[(size_t)(m0 + m) * 128 + k0 + k];
        }
#pragma unroll
        for (int i = 0; i < 8; i++) {
            int l = threadIdx.x + i * 256;
            int k = l >> 6, n = l & 63;
            Bs1[k * 64 + n] = Wao[(k0 + k) * 128 + n0 + n];
            Bs2[k * 64 + n] = Wg[(k0 + k) * 128 + n0 + n];
        }
        __syncthreads();
#pragma unroll
        for (int k = 0; k < 32; k++) {
            float a1[4], a2[4], b1v[4], b2v[4];
#pragma unroll
            for (int i = 0; i < 4; i++) { a1[i] = As1[k * 65 + ty * 4 + i]; a2[i] = As2[k * 65 + ty * 4 + i]; }
#pragma unroll
            for (int j = 0; j < 4; j++) { b1v[j] = Bs1[k * 64 + tx * 4 + j]; b2v[j] = Bs2[k * 64 + tx * 4 + j]; }
#pragma unroll
            for (int i = 0; i < 4; i++)
#pragma unroll
                for (int j = 0; j < 4; j++) {
                    acc1[i][j] += a1[i] * b1v[j];
                    acc2[i][j] += a2[i] * b2v[j];
                }
        }
        __syncthreads();
    }
#pragma unroll
    for (int i = 0; i < 4; i++) {
        int m = m0 + ty * 4 + i;
#pragma unroll
        for (int j = 0; j < 4; j++) {
            int n = n0 + tx * 4 + j;
            float t1 = acc1[i][j] + bao[n];
            float gg = 1.f / (1.f + __expf(-(acc2[i][j] + bg[n])));
            float u = g_upd[(size_t)m * 128 + n];
            g_mix[(size_t)m * 128 + n] = gg * t1 + (1.f - gg) * u;
        }
    }
}

// ---------------- launch ----------------
extern "C" void kernel_launch(void* const* d_in, const int* in_sizes, int n_in,
                              void* d_out, int out_size) {
    const int*   an    = (const int*)d_in[0];
    const int*   ei    = (const int*)d_in[2];
    const float* ev    = (const float*)d_in[3];
    const float* el    = (const float*)d_in[4];
    const float* emb   = (const float*)d_in[5];
    const float* W_r1  = (const float*)d_in[6];  const float* b_r1 = (const float*)d_in[7];
    const float* W_r2  = (const float*)d_in[8];  const float* b_r2 = (const float*)d_in[9];
    const float* W_tp  = (const float*)d_in[10]; const float* b_tp = (const float*)d_in[11];
    const float* W_m1  = (const float*)d_in[12]; const float* b_m1 = (const float*)d_in[13];
    const float* W_m2  = (const float*)d_in[14]; const float* b_m2 = (const float*)d_in[15];
    const float* W_qkv = (const float*)d_in[16]; const float* b_qkv= (const float*)d_in[17];
    const float* W_ao  = (const float*)d_in[18]; const float* b_ao = (const float*)d_in[19];
    const float* W_g   = (const float*)d_in[20]; const float* b_g  = (const float*)d_in[21];
    const float* W_o   = (const float*)d_in[22]; const float* b_o  = (const float*)d_in[23];
    float* out = (float*)d_out;

    float *p_comb, *p_hid, *p_upd, *p_qkv, *p_mix;
    cudaGetSymbolAddress((void**)&p_comb, g_comb);
    cudaGetSymbolAddress((void**)&p_hid,  g_hid);
    cudaGetSymbolAddress((void**)&p_upd,  g_upd);
    cudaGetSymbolAddress((void**)&p_qkv,  g_qkv);
    cudaGetSymbolAddress((void**)&p_mix,  g_mix);

    zero_hist_kernel<<<16, 256>>>();
    hist_kernel<<<512, 256>>>(ei);
    edge_fused_kernel<<<512, 256>>>(ev, el, W_r1, b_r1, W_r2, b_r2);
    scan_kernel<<<1, 1024>>>();
    scatter_kernel<<<512, 256>>>(ei);
    aggregate_kernel<<<NA, 128>>>();
    embed_kernel<<<NA * 128 / 256, 256>>>(an, emb, b_tp);
    agg_gemm_kernel<<<dim3(NA / 64, 4), 256>>>(W_tp);
    gemm_kernel<<<dim3(NA / 64, 2), 256>>>(p_comb, W_m1, b_m1, p_hid, NA, 128, 128, 1);
    gemm_kernel<<<dim3(NA / 64, 2), 256>>>(p_hid, W_m2, b_m2, p_upd, NA, 128, 128, 0);
    gemm_kernel<<<dim3(NA / 64, 6), 256>>>(p_upd, W_qkv, b_qkv, p_qkv, NA, 384, 128, 0);
    attn_kernel<<<dim3(NA / 64, 4), 64>>>();
    gemm_dual_kernel<<<dim3(NA / 64, 2), 256>>>(W_ao, b_ao, W_g, b_g);
    gemm_kernel<<<dim3(NA / 64, 2), 256>>>(p_mix, W_o, b_o, out, NA, 128, 128, 0);
}

// round 4
// speedup vs baseline: 1.6087x; 1.4886x over previous
#include <cuda_runtime.h>
#include <math.h>

#define NA   4096
#define NE   131072
#define TPIN 1152
#define SPLIT 8
#define KCHUNK (NA / SPLIT)

typedef unsigned long long u64t;

__device__ __forceinline__ u64t pk2(float a, float b) {
    u64t r; asm("mov.b64 %0,{%1,%2};" : "=l"(r) : "f"(a), "f"(b)); return r;
}
__device__ __forceinline__ void upk2(u64t v, float& a, float& b) {
    asm("mov.b64 {%0,%1},%2;" : "=f"(a), "=f"(b) : "l"(v));
}
__device__ __forceinline__ u64t ffma2(u64t a, u64t b, u64t c) {
    u64t d; asm("fma.rn.f32x2 %0,%1,%2,%3;" : "=l"(d) : "l"(a), "l"(b), "l"(c)); return d;
}
__device__ __forceinline__ u64t fmul2(u64t a, u64t b) {
    u64t d; asm("mul.rn.f32x2 %0,%1,%2;" : "=l"(d) : "l"(a), "l"(b)); return d;
}

// ---------------- scratch ----------------
__device__ float g_sh[NE * 9];
__device__ float g_rad[(size_t)NE * 128];
__device__ int   g_hist[NA];
__device__ int   g_off[NA];
__device__ int   g_cur[NA];
__device__ int   g_elist[NE];
__device__ float g_A[(size_t)NA * TPIN];
__device__ float g_comb[NA * 128];
__device__ float g_hid[NA * 128];
__device__ float g_upd[NA * 128];
__device__ float g_qkv[NA * 384];
__device__ float g_att[NA * 128];
__device__ float g_mix[NA * 128];
__device__ float g_pO[(size_t)SPLIT * NA * 128];
__device__ float g_pml[(size_t)SPLIT * NA * 4 * 2];

// ---------------- fused edge kernel ----------------
__global__ __launch_bounds__(256) void edge_fused_kernel(
        const float* __restrict__ ev, const float* __restrict__ el,
        const float* __restrict__ W1, const float* __restrict__ b1,
        const float* __restrict__ W2, const float* __restrict__ b2) {
    __shared__ float sW1[8 * 64];
    __shared__ float sb1[64];
    __shared__ __align__(16) float sW2[64 * 128];
    __shared__ float sb2[128];
    for (int i = threadIdx.x; i < 512;  i += 256) sW1[i] = W1[i];
    for (int i = threadIdx.x; i < 64;   i += 256) sb1[i] = b1[i];
    for (int i = threadIdx.x; i < 8192; i += 256) sW2[i] = W2[i];
    for (int i = threadIdx.x; i < 128;  i += 256) sb2[i] = b2[i];
    __syncthreads();

    int warp = threadIdx.x >> 5, lane = threadIdx.x & 31;
    const float PIC = 3.14159265358979323846f / 6.0f;
    for (int it = 0; it < NE / 4096; it++) {
        int e = blockIdx.x * 8 + warp + it * 4096;
        float vx = ev[e * 3 + 0], vy = ev[e * 3 + 1], vz = ev[e * 3 + 2];
        float l = el[e];
        float r = sqrtf(vx * vx + vy * vy + vz * vz) + 1e-8f;
        float x = vx / r, y = vy / r, z = vz / r;
        if (lane < 9) {
            float s;
            switch (lane) {
                case 0: s = 1.f; break;
                case 1: s = y; break;
                case 2: s = z; break;
                case 3: s = x; break;
                case 4: s = 3.f * z * z - 1.f; break;
                case 5: s = x * z; break;
                case 6: s = y * z; break;
                case 7: s = x * y; break;
                default: s = x * x - y * y; break;
            }
            g_sh[e * 9 + lane] = s;
        }
        float env = 0.5f * (__cosf(l * PIC) + 1.f) * (l < 6.0f ? 1.f : 0.f);
        float inv_l_env = env / l;
        float rb[8];
#pragma unroll
        for (int b = 0; b < 8; b++) rb[b] = __sinf(l * (float)(b + 1) * PIC) * inv_l_env;
        float h1a = sb1[lane], h1b = sb1[lane + 32];
#pragma unroll
        for (int b = 0; b < 8; b++) {
            h1a += rb[b] * sW1[b * 64 + lane];
            h1b += rb[b] * sW1[b * 64 + lane + 32];
        }
        h1a = h1a / (1.f + __expf(-h1a));
        h1b = h1b / (1.f + __expf(-h1b));
        u64t acc0 = pk2(sb2[lane * 4 + 0], sb2[lane * 4 + 1]);
        u64t acc1 = pk2(sb2[lane * 4 + 2], sb2[lane * 4 + 3]);
#pragma unroll
        for (int k = 0; k < 64; k++) {
            float hk = (k < 32) ? __shfl_sync(0xffffffffu, h1a, k)
                                : __shfl_sync(0xffffffffu, h1b, k - 32);
            u64t hk2 = pk2(hk, hk);
            ulonglong2 w = *(const ulonglong2*)&sW2[k * 128 + lane * 4];
            acc0 = ffma2(hk2, w.x, acc0);
            acc1 = ffma2(hk2, w.y, acc1);
        }
        float o0, o1, o2, o3;
        upk2(acc0, o0, o1); upk2(acc1, o2, o3);
        o0 = o0 / (1.f + __expf(-o0));
        o1 = o1 / (1.f + __expf(-o1));
        o2 = o2 / (1.f + __expf(-o2));
        o3 = o3 / (1.f + __expf(-o3));
        *(float4*)&g_rad[(size_t)e * 128 + lane * 4] = make_float4(o0, o1, o2, o3);
    }
}

// ---------------- generic tiled fp32 GEMM ----------------
__global__ void gemm_kernel(const float* __restrict__ A, const float* __restrict__ W,
                            const float* __restrict__ bias, float* __restrict__ C,
                            int M, int N, int K, int act) {
    __shared__ float As[32 * 65];
    __shared__ float Bs[32 * 64];
    int tx = threadIdx.x & 15, ty = threadIdx.x >> 4;
    int m0 = blockIdx.x * 64, n0 = blockIdx.y * 64;
    float acc[4][4] = {};
    for (int k0 = 0; k0 < K; k0 += 32) {
#pragma unroll
        for (int i = 0; i < 8; i++) {
            int l = threadIdx.x + i * 256;
            int m = l >> 5, k = l & 31;
            As[k * 65 + m] = A[(size_t)(m0 + m) * K + k0 + k];
        }
#pragma unroll
        for (int i = 0; i < 8; i++) {
            int l = threadIdx.x + i * 256;
            int k = l >> 6, n = l & 63;
            Bs[k * 64 + n] = W[(size_t)(k0 + k) * N + n0 + n];
        }
        __syncthreads();
#pragma unroll
        for (int k = 0; k < 32; k++) {
            float a[4], b[4];
#pragma unroll
            for (int i = 0; i < 4; i++) a[i] = As[k * 65 + ty * 4 + i];
#pragma unroll
            for (int j = 0; j < 4; j++) b[j] = Bs[k * 64 + tx * 4 + j];
#pragma unroll
            for (int i = 0; i < 4; i++)
#pragma unroll
                for (int j = 0; j < 4; j++) acc[i][j] += a[i] * b[j];
        }
        __syncthreads();
    }
#pragma unroll
    for (int i = 0; i < 4; i++) {
        int m = m0 + ty * 4 + i;
#pragma unroll
        for (int j = 0; j < 4; j++) {
            int n = n0 + tx * 4 + j;
            float v = acc[i][j] + bias[n];
            if (act == 1) v = v / (1.f + __expf(-v));
            else if (act == 2) v = 1.f / (1.f + __expf(-v));
            C[(size_t)m * N + n] = v;
        }
    }
}

// ---------------- CSR build ----------------
__global__ void zero_hist_kernel() {
    int i = blockIdx.x * blockDim.x + threadIdx.x;
    if (i < NA) g_hist[i] = 0;
}
__global__ void hist_kernel(const int* __restrict__ ei) {
    for (int e = blockIdx.x * blockDim.x + threadIdx.x; e < NE; e += gridDim.x * blockDim.x)
        atomicAdd(&g_hist[ei[NE + e]], 1);
}
__global__ void scan_kernel() {
    __shared__ int s[1024];
    int t = threadIdx.x;
    int v0 = g_hist[t * 4], v1 = g_hist[t * 4 + 1], v2 = g_hist[t * 4 + 2], v3 = g_hist[t * 4 + 3];
    int sum = v0 + v1 + v2 + v3;
    s[t] = sum;
    __syncthreads();
    for (int d = 1; d < 1024; d <<= 1) {
        int add = (t >= d) ? s[t - d] : 0;
        __syncthreads();
        s[t] += add;
        __syncthreads();
    }
    int base = s[t] - sum;
    g_off[t * 4 + 0] = base;                 g_cur[t * 4 + 0] = base;
    g_off[t * 4 + 1] = base + v0;            g_cur[t * 4 + 1] = base + v0;
    g_off[t * 4 + 2] = base + v0 + v1;       g_cur[t * 4 + 2] = base + v0 + v1;
    g_off[t * 4 + 3] = base + v0 + v1 + v2;  g_cur[t * 4 + 3] = base + v0 + v1 + v2;
}
__global__ void scatter_kernel(const int* __restrict__ ei) {
    for (int e = blockIdx.x * blockDim.x + threadIdx.x; e < NE; e += gridDim.x * blockDim.x) {
        int d = ei[NE + e];
        int p = atomicAdd(&g_cur[d], 1);
        g_elist[p] = e;
    }
}

// ---------------- per-node rank-1 aggregation ----------------
__global__ void aggregate_kernel() {
    int n = blockIdx.x;
    int c = threadIdx.x;  // 128
    int start = g_off[n], cnt = g_hist[n];
    __shared__ int   eid[32];
    __shared__ float shs[32 * 9];
    float acc[9] = {};
    for (int base = 0; base < cnt; base += 32) {
        int m = min(32, cnt - base);
        if (c < m) eid[c] = g_elist[start + base + c];
        __syncthreads();
        for (int j = c; j < m * 9; j += 128) shs[j] = g_sh[(size_t)eid[j / 9] * 9 + j % 9];
        __syncthreads();
        for (int i = 0; i < m; i++) {
            float rv = g_rad[(size_t)eid[i] * 128 + c];
#pragma unroll
            for (int s = 0; s < 9; s++) acc[s] += rv * shs[i * 9 + s];
        }
        __syncthreads();
    }
    size_t b = (size_t)n * TPIN;
    g_A[b + c] = acc[0];
#pragma unroll
    for (int s = 1; s < 4; s++) g_A[b + 128 + c * 3 + (s - 1)] = acc[s];
#pragma unroll
    for (int s = 4; s < 9; s++) g_A[b + 512 + c * 5 + (s - 4)] = acc[s];
}

// ---------------- embed + bias*deg init of g_comb ----------------
__global__ void embed_kernel(const int* __restrict__ an, const float* __restrict__ emb,
                             const float* __restrict__ btp) {
    int i = blockIdx.x * blockDim.x + threadIdx.x;
    if (i < NA * 128) {
        int n = i >> 7, j = i & 127;
        g_comb[i] = (j < 64) ? emb[an[n] * 64 + j]
                             : btp[j - 64] * (float)g_hist[n];
    }
}

// ---------------- split-K GEMM: g_A @ W_tp[:, :64] ----------------
__global__ void agg_gemm_kernel(const float* __restrict__ Wtp) {
    __shared__ float As[32 * 65];
    __shared__ float Bs[32 * 64];
    int tx = threadIdx.x & 15, ty = threadIdx.x >> 4;
    int m0 = blockIdx.x * 64;
    int kb = blockIdx.y * 288;
    float acc[4][4] = {};
    for (int k0 = 0; k0 < 288; k0 += 32) {
#pragma unroll
        for (int i = 0; i < 8; i++) {
            int l = threadIdx.x + i * 256;
            int m = l >> 5, k = l & 31;
            As[k * 65 + m] = g_A[(size_t)(m0 + m) * TPIN + kb + k0 + k];
        }
#pragma unroll
        for (int i = 0; i < 8; i++) {
            int l = threadIdx.x + i * 256;
            int k = l >> 6, n = l & 63;
            Bs[k * 64 + n] = Wtp[(kb + k0 + k) * 128 + n];
        }
        __syncthreads();
#pragma unroll
        for (int k = 0; k < 32; k++) {
            float a[4], b[4];
#pragma unroll
            for (int i = 0; i < 4; i++) a[i] = As[k * 65 + ty * 4 + i];
#pragma unroll
            for (int j = 0; j < 4; j++) b[j] = Bs[k * 64 + tx * 4 + j];
#pragma unroll
            for (int i = 0; i < 4; i++)
#pragma unroll
                for (int j = 0; j < 4; j++) acc[i][j] += a[i] * b[j];
        }
        __syncthreads();
    }
#pragma unroll
    for (int i = 0; i < 4; i++) {
        int m = m0 + ty * 4 + i;
#pragma unroll
        for (int j = 0; j < 4; j++) {
            int n = tx * 4 + j;
            atomicAdd(&g_comb[m * 128 + 64 + n], acc[i][j]);
        }
    }
}

// ---------------- split-KV attention partials ----------------
// grid (NA/128, 4 heads, SPLIT), block 128; thread = query
__global__ __launch_bounds__(128) void attn_part_kernel() {
    __shared__ __align__(16) float Ks[32][32];
    __shared__ __align__(16) float Vs[32][32];
    int t = threadIdx.x;
    int h = blockIdx.y;
    int sp = blockIdx.z;
    int qi = blockIdx.x * 128 + t;
    const float sc = 0.17677669529663687f;  // 1/sqrt(32)
    u64t q2[16], O2[16];
    const float4* qp = (const float4*)&g_qkv[(size_t)qi * 384 + h * 32];
#pragma unroll
    for (int i = 0; i < 8; i++) {
        float4 v = qp[i];
        q2[2 * i]     = pk2(v.x * sc, v.y * sc);
        q2[2 * i + 1] = pk2(v.z * sc, v.w * sc);
    }
#pragma unroll
    for (int i = 0; i < 16; i++) O2[i] = 0ull;
    float M = -1e30f, L = 0.f;
    for (int m0 = sp * KCHUNK; m0 < (sp + 1) * KCHUNK; m0 += 32) {
#pragma unroll
        for (int i = 0; i < 2; i++) {
            int u = t + i * 128;
            int j = u >> 3, dd = (u & 7) * 4;
            *(float4*)&Ks[j][dd] = *(const float4*)&g_qkv[(size_t)(m0 + j) * 384 + 128 + h * 32 + dd];
            *(float4*)&Vs[j][dd] = *(const float4*)&g_qkv[(size_t)(m0 + j) * 384 + 256 + h * 32 + dd];
        }
        __syncthreads();
        float s[32];
#pragma unroll
        for (int j = 0; j < 32; j++) {
            const ulonglong2* kp = (const ulonglong2*)&Ks[j][0];
            u64t a0 = 0ull, a1 = 0ull;
#pragma unroll
            for (int i = 0; i < 8; i++) {
                ulonglong2 kk = kp[i];
                a0 = ffma2(q2[2 * i], kk.x, a0);
                a1 = ffma2(q2[2 * i + 1], kk.y, a1);
            }
            float lo0, hi0, lo1, hi1;
            upk2(a0, lo0, hi0); upk2(a1, lo1, hi1);
            s[j] = (lo0 + hi0) + (lo1 + hi1);
        }
        float cm = s[0];
#pragma unroll
        for (int j = 1; j < 32; j++) cm = fmaxf(cm, s[j]);
        float Mn = fmaxf(M, cm);
        float scal = __expf(M - Mn);
        float ps = 0.f;
#pragma unroll
        for (int j = 0; j < 32; j++) { s[j] = __expf(s[j] - Mn); ps += s[j]; }
        L = L * scal + ps;
        M = Mn;
        u64t scal2 = pk2(scal, scal);
#pragma unroll
        for (int i = 0; i < 16; i++) O2[i] = fmul2(O2[i], scal2);
#pragma unroll
        for (int j = 0; j < 32; j++) {
            u64t pp = pk2(s[j], s[j]);
            const ulonglong2* vp = (const ulonglong2*)&Vs[j][0];
#pragma unroll
            for (int i = 0; i < 8; i++) {
                ulonglong2 vv = vp[i];
                O2[2 * i]     = ffma2(pp, vv.x, O2[2 * i]);
                O2[2 * i + 1] = ffma2(pp, vv.y, O2[2 * i + 1]);
            }
        }
        __syncthreads();
    }
    size_t base = (size_t)sp * NA + qi;
    float* op = &g_pO[base * 128 + h * 32];
#pragma unroll
    for (int i = 0; i < 8; i++) {
        float a, b, c, d;
        upk2(O2[2 * i], a, b); upk2(O2[2 * i + 1], c, d);
        *(float4*)&op[i * 4] = make_float4(a, b, c, d);
    }
    g_pml[(base * 4 + h) * 2 + 0] = M;
    g_pml[(base * 4 + h) * 2 + 1] = L;
}

// ---------------- combine split-KV partials ----------------
__global__ void attn_combine_kernel() {
    int i = blockIdx.x * blockDim.x + threadIdx.x;
    if (i >= NA * 128) return;
    int qi = i >> 7, hd = i & 127, h = hd >> 5;
    float m[SPLIT], l[SPLIT];
    float M = -1e30f;
#pragma unroll
    for (int s = 0; s < SPLIT; s++) {
        size_t base = (size_t)s * NA + qi;
        m[s] = g_pml[(base * 4 + h) * 2 + 0];
        l[s] = g_pml[(base * 4 + h) * 2 + 1];
        M = fmaxf(M, m[s]);
    }
    float L = 0.f, O = 0.f;
#pragma unroll
    for (int s = 0; s < SPLIT; s++) {
        float w = __expf(m[s] - M);
        L += l[s] * w;
        O += g_pO[((size_t)s * NA + qi) * 128 + hd] * w;
    }
    g_att[i] = O / L;
}

// ---------------- fused: t1 = att@Wao+bao; g = sig(upd@Wg+bg); mix ---------
__global__ void gemm_dual_kernel(const float* __restrict__ Wao, const float* __restrict__ bao,
                                 const float* __restrict__ Wg,  const float* __restrict__ bg) {
    __shared__ float As1[32 * 65];
    __shared__ float As2[32 * 65];
    __shared__ float Bs1[32 * 64];
    __shared__ float Bs2[32 * 64];
    int tx = threadIdx.x & 15, ty = threadIdx.x >> 4;
    int m0 = blockIdx.x * 64, n0 = blockIdx.y * 64;
    float acc1[4][4] = {}, acc2[4][4] = {};
    for (int k0 = 0; k0 < 128; k0 += 32) {
#pragma unroll
        for (int i = 0; i < 8; i++) {
            int l = threadIdx.x + i * 256;
            int m = l >> 5, k = l & 31;
            As1[k * 65 + m] = g_att[(size_t)(m0 + m) * 128 + k0 + k];
            As2[k * 65 + m] = g_upd[(size_t)(m0 + m) * 128 + k0 + k];
        }
#pragma unroll
        for (int i = 0; i < 8; i++) {
            int l = threadIdx.x + i * 256;
            int k = l >> 6, n = l & 63;
            Bs1[k * 64 + n] = Wao[(k0 + k) * 128 + n0 + n];
            Bs2[k * 64 + n] = Wg[(k0 + k) * 128 + n0 + n];
        }
        __syncthreads();
#pragma unroll
        for (int k = 0; k < 32; k++) {
            float a1[4], a2[4], b1v[4], b2v[4];
#pragma unroll
            for (int i = 0; i < 4; i++) { a1[i] = As1[k * 65 + ty * 4 + i]; a2[i] = As2[k * 65 + ty * 4 + i]; }
#pragma unroll
            for (int j = 0; j < 4; j++) { b1v[j] = Bs1[k * 64 + tx * 4 + j]; b2v[j] = Bs2[k * 64 + tx * 4 + j]; }
#pragma unroll
            for (int i = 0; i < 4; i++)
#pragma unroll
                for (int j = 0; j < 4; j++) {
                    acc1[i][j] += a1[i] * b1v[j];
                    acc2[i][j] += a2[i] * b2v[j];
                }
        }
        __syncthreads();
    }
#pragma unroll
    for (int i = 0; i < 4; i++) {
        int m = m0 + ty * 4 + i;
#pragma unroll
        for (int j = 0; j < 4; j++) {
            int n = n0 + tx * 4 + j;
            float t1 = acc1[i][j] + bao[n];
            float gg = 1.f / (1.f + __expf(-(acc2[i][j] + bg[n])));
            float u = g_upd[(size_t)m * 128 + n];
            g_mix[(size_t)m * 128 + n] = gg * t1 + (1.f - gg) * u;
        }
    }
}

// ---------------- launch ----------------
extern "C" void kernel_launch(void* const* d_in, const int* in_sizes, int n_in,
                              void* d_out, int out_size) {
    const int*   an    = (const int*)d_in[0];
    const int*   ei    = (const int*)d_in[2];
    const float* ev    = (const float*)d_in[3];
    const float* el    = (const float*)d_in[4];
    const float* emb   = (const float*)d_in[5];
    const float* W_r1  = (const float*)d_in[6];  const float* b_r1 = (const float*)d_in[7];
    const float* W_r2  = (const float*)d_in[8];  const float* b_r2 = (const float*)d_in[9];
    const float* W_tp  = (const float*)d_in[10]; const float* b_tp = (const float*)d_in[11];
    const float* W_m1  = (const float*)d_in[12]; const float* b_m1 = (const float*)d_in[13];
    const float* W_m2  = (const float*)d_in[14]; const float* b_m2 = (const float*)d_in[15];
    const float* W_qkv = (const float*)d_in[16]; const float* b_qkv= (const float*)d_in[17];
    const float* W_ao  = (const float*)d_in[18]; const float* b_ao = (const float*)d_in[19];
    const float* W_g   = (const float*)d_in[20]; const float* b_g  = (const float*)d_in[21];
    const float* W_o   = (const float*)d_in[22]; const float* b_o  = (const float*)d_in[23];
    float* out = (float*)d_out;

    float *p_comb, *p_hid, *p_upd, *p_qkv, *p_mix;
    cudaGetSymbolAddress((void**)&p_comb, g_comb);
    cudaGetSymbolAddress((void**)&p_hid,  g_hid);
    cudaGetSymbolAddress((void**)&p_upd,  g_upd);
    cudaGetSymbolAddress((void**)&p_qkv,  g_qkv);
    cudaGetSymbolAddress((void**)&p_mix,  g_mix);

    zero_hist_kernel<<<16, 256>>>();
    hist_kernel<<<512, 256>>>(ei);
    edge_fused_kernel<<<512, 256>>>(ev, el, W_r1, b_r1, W_r2, b_r2);
    scan_kernel<<<1, 1024>>>();
    scatter_kernel<<<512, 256>>>(ei);
    aggregate_kernel<<<NA, 128>>>();
    embed_kernel<<<NA * 128 / 256, 256>>>(an, emb, b_tp);
    agg_gemm_kernel<<<dim3(NA / 64, 4), 256>>>(W_tp);
    gemm_kernel<<<dim3(NA / 64, 2), 256>>>(p_comb, W_m1, b_m1, p_hid, NA, 128, 128, 1);
    gemm_kernel<<<dim3(NA / 64, 2), 256>>>(p_hid, W_m2, b_m2, p_upd, NA, 128, 128, 0);
    gemm_kernel<<<dim3(NA / 64, 6), 256>>>(p_upd, W_qkv, b_qkv, p_qkv, NA, 384, 128, 0);
    attn_part_kernel<<<dim3(NA / 128, 4, SPLIT), 128>>>();
    attn_combine_kernel<<<NA * 128 / 256, 256>>>();
    gemm_dual_kernel<<<dim3(NA / 64, 2), 256>>>(W_ao, b_ao, W_g, b_g);
    gemm_kernel<<<dim3(NA / 64, 2), 256>>>(p_mix, W_o, b_o, out, NA, 128, 128, 0);
}

// round 6
// speedup vs baseline: 2.3476x; 1.4593x over previous
#include <cuda_runtime.h>
#include <math.h>
#include <stdint.h>

#define NA   4096
#define NE   131072
#define TPIN 1152
#define SPLIT 2

typedef unsigned long long u64t;

__device__ __forceinline__ u64t pk2(float a, float b) {
    u64t r; asm("mov.b64 %0,{%1,%2};" : "=l"(r) : "f"(a), "f"(b)); return r;
}
__device__ __forceinline__ void upk2(u64t v, float& a, float& b) {
    asm("mov.b64 {%0,%1},%2;" : "=f"(a), "=f"(b) : "l"(v));
}
__device__ __forceinline__ u64t ffma2(u64t a, u64t b, u64t c) {
    u64t d; asm("fma.rn.f32x2 %0,%1,%2,%3;" : "=l"(d) : "l"(a), "l"(b), "l"(c)); return d;
}
__device__ __forceinline__ uint32_t tf32r(float f) {
    uint32_t u; asm("cvt.rna.tf32.f32 %0,%1;" : "=r"(u) : "f"(f)); return u;
}
__device__ __forceinline__ void mma_tf32(float* c, const uint32_t* a, uint32_t b0, uint32_t b1) {
    asm volatile("mma.sync.aligned.m16n8k8.row.col.f32.tf32.tf32.f32 "
        "{%0,%1,%2,%3},{%4,%5,%6,%7},{%8,%9},{%0,%1,%2,%3};"
        : "+f"(c[0]), "+f"(c[1]), "+f"(c[2]), "+f"(c[3])
        : "r"(a[0]), "r"(a[1]), "r"(a[2]), "r"(a[3]), "r"(b0), "r"(b1));
}

// ---------------- scratch ----------------
__device__ float g_sh[NE * 9];
__device__ float g_rad[(size_t)NE * 128];
__device__ int   g_hist[NA];
__device__ int   g_off[NA];
__device__ int   g_cur[NA];
__device__ int   g_elist[NE];
__device__ float g_A[(size_t)NA * TPIN];
__device__ float g_comb[NA * 128];
__device__ float g_hid[NA * 128];
__device__ float g_upd[NA * 128];
__device__ float g_qkv[NA * 384];
__device__ float g_att[NA * 128];
__device__ float g_mix[NA * 128];
__device__ float g_pO[(size_t)SPLIT * NA * 128];
__device__ float g_pml[(size_t)SPLIT * NA * 4 * 2];

// ---------------- fused edge kernel ----------------
__global__ __launch_bounds__(256) void edge_fused_kernel(
        const float* __restrict__ ev, const float* __restrict__ el,
        const float* __restrict__ W1, const float* __restrict__ b1,
        const float* __restrict__ W2, const float* __restrict__ b2) {
    __shared__ float sW1[8 * 64];
    __shared__ float sb1[64];
    __shared__ __align__(16) float sW2[64 * 128];
    __shared__ float sb2[128];
    for (int i = threadIdx.x; i < 512;  i += 256) sW1[i] = W1[i];
    for (int i = threadIdx.x; i < 64;   i += 256) sb1[i] = b1[i];
    for (int i = threadIdx.x; i < 8192; i += 256) sW2[i] = W2[i];
    for (int i = threadIdx.x; i < 128;  i += 256) sb2[i] = b2[i];
    __syncthreads();

    int warp = threadIdx.x >> 5, lane = threadIdx.x & 31;
    const float PIC = 3.14159265358979323846f / 6.0f;
    for (int it = 0; it < NE / 4096; it++) {
        int e = blockIdx.x * 8 + warp + it * 4096;
        float vx = ev[e * 3 + 0], vy = ev[e * 3 + 1], vz = ev[e * 3 + 2];
        float l = el[e];
        float r = sqrtf(vx * vx + vy * vy + vz * vz) + 1e-8f;
        float x = vx / r, y = vy / r, z = vz / r;
        if (lane < 9) {
            float s;
            switch (lane) {
                case 0: s = 1.f; break;
                case 1: s = y; break;
                case 2: s = z; break;
                case 3: s = x; break;
                case 4: s = 3.f * z * z - 1.f; break;
                case 5: s = x * z; break;
                case 6: s = y * z; break;
                case 7: s = x * y; break;
                default: s = x * x - y * y; break;
            }
            g_sh[e * 9 + lane] = s;
        }
        float env = 0.5f * (__cosf(l * PIC) + 1.f) * (l < 6.0f ? 1.f : 0.f);
        float inv_l_env = env / l;
        float rb[8];
#pragma unroll
        for (int b = 0; b < 8; b++) rb[b] = __sinf(l * (float)(b + 1) * PIC) * inv_l_env;
        float h1a = sb1[lane], h1b = sb1[lane + 32];
#pragma unroll
        for (int b = 0; b < 8; b++) {
            h1a += rb[b] * sW1[b * 64 + lane];
            h1b += rb[b] * sW1[b * 64 + lane + 32];
        }
        h1a = h1a / (1.f + __expf(-h1a));
        h1b = h1b / (1.f + __expf(-h1b));
        u64t acc0 = pk2(sb2[lane * 4 + 0], sb2[lane * 4 + 1]);
        u64t acc1 = pk2(sb2[lane * 4 + 2], sb2[lane * 4 + 3]);
#pragma unroll
        for (int k = 0; k < 64; k++) {
            float hk = (k < 32) ? __shfl_sync(0xffffffffu, h1a, k)
                                : __shfl_sync(0xffffffffu, h1b, k - 32);
            u64t hk2 = pk2(hk, hk);
            ulonglong2 w = *(const ulonglong2*)&sW2[k * 128 + lane * 4];
            acc0 = ffma2(hk2, w.x, acc0);
            acc1 = ffma2(hk2, w.y, acc1);
        }
        float o0, o1, o2, o3;
        upk2(acc0, o0, o1); upk2(acc1, o2, o3);
        o0 = o0 / (1.f + __expf(-o0));
        o1 = o1 / (1.f + __expf(-o1));
        o2 = o2 / (1.f + __expf(-o2));
        o3 = o3 / (1.f + __expf(-o3));
        *(float4*)&g_rad[(size_t)e * 128 + lane * 4] = make_float4(o0, o1, o2, o3);
    }
}

// ---------------- generic tiled fp32 GEMM ----------------
__global__ void gemm_kernel(const float* __restrict__ A, const float* __restrict__ W,
                            const float* __restrict__ bias, float* __restrict__ C,
                            int M, int N, int K, int act) {
    __shared__ float As[32 * 65];
    __shared__ float Bs[32 * 64];
    int tx = threadIdx.x & 15, ty = threadIdx.x >> 4;
    int m0 = blockIdx.x * 64, n0 = blockIdx.y * 64;
    float acc[4][4] = {};
    for (int k0 = 0; k0 < K; k0 += 32) {
#pragma unroll
        for (int i = 0; i < 8; i++) {
            int l = threadIdx.x + i * 256;
            int m = l >> 5, k = l & 31;
            As[k * 65 + m] = A[(size_t)(m0 + m) * K + k0 + k];
        }
#pragma unroll
        for (int i = 0; i < 8; i++) {
            int l = threadIdx.x + i * 256;
            int k = l >> 6, n = l & 63;
            Bs[k * 64 + n] = W[(size_t)(k0 + k) * N + n0 + n];
        }
        __syncthreads();
#pragma unroll
        for (int k = 0; k < 32; k++) {
            float a[4], b[4];
#pragma unroll
            for (int i = 0; i < 4; i++) a[i] = As[k * 65 + ty * 4 + i];
#pragma unroll
            for (int j = 0; j < 4; j++) b[j] = Bs[k * 64 + tx * 4 + j];
#pragma unroll
            for (int i = 0; i < 4; i++)
#pragma unroll
                for (int j = 0; j < 4; j++) acc[i][j] += a[i] * b[j];
        }
        __syncthreads();
    }
#pragma unroll
    for (int i = 0; i < 4; i++) {
        int m = m0 + ty * 4 + i;
#pragma unroll
        for (int j = 0; j < 4; j++) {
            int n = n0 + tx * 4 + j;
            float v = acc[i][j] + bias[n];
            if (act == 1) v = v / (1.f + __expf(-v));
            else if (act == 2) v = 1.f / (1.f + __expf(-v));
            C[(size_t)m * N + n] = v;
        }
    }
}

// ---------------- CSR build ----------------
__global__ void zero_hist_kernel() {
    int i = blockIdx.x * blockDim.x + threadIdx.x;
    if (i < NA) g_hist[i] = 0;
}
__global__ void hist_kernel(const int* __restrict__ ei) {
    for (int e = blockIdx.x * blockDim.x + threadIdx.x; e < NE; e += gridDim.x * blockDim.x)
        atomicAdd(&g_hist[ei[NE + e]], 1);
}
__global__ void scan_kernel() {
    __shared__ int s[1024];
    int t = threadIdx.x;
    int v0 = g_hist[t * 4], v1 = g_hist[t * 4 + 1], v2 = g_hist[t * 4 + 2], v3 = g_hist[t * 4 + 3];
    int sum = v0 + v1 + v2 + v3;
    s[t] = sum;
    __syncthreads();
    for (int d = 1; d < 1024; d <<= 1) {
        int add = (t >= d) ? s[t - d] : 0;
        __syncthreads();
        s[t] += add;
        __syncthreads();
    }
    int base = s[t] - sum;
    g_off[t * 4 + 0] = base;                 g_cur[t * 4 + 0] = base;
    g_off[t * 4 + 1] = base + v0;            g_cur[t * 4 + 1] = base + v0;
    g_off[t * 4 + 2] = base + v0 + v1;       g_cur[t * 4 + 2] = base + v0 + v1;
    g_off[t * 4 + 3] = base + v0 + v1 + v2;  g_cur[t * 4 + 3] = base + v0 + v1 + v2;
}
__global__ void scatter_kernel(const int* __restrict__ ei) {
    for (int e = blockIdx.x * blockDim.x + threadIdx.x; e < NE; e += gridDim.x * blockDim.x) {
        int d = ei[NE + e];
        int p = atomicAdd(&g_cur[d], 1);
        g_elist[p] = e;
    }
}

// ---------------- per-node rank-1 aggregation ----------------
__global__ void aggregate_kernel() {
    int n = blockIdx.x;
    int c = threadIdx.x;  // 128
    int start = g_off[n], cnt = g_hist[n];
    __shared__ int   eid[32];
    __shared__ float shs[32 * 9];
    float acc[9] = {};
    for (int base = 0; base < cnt; base += 32) {
        int m = min(32, cnt - base);
        if (c < m) eid[c] = g_elist[start + base + c];
        __syncthreads();
        for (int j = c; j < m * 9; j += 128) shs[j] = g_sh[(size_t)eid[j / 9] * 9 + j % 9];
        __syncthreads();
        for (int i = 0; i < m; i++) {
            float rv = g_rad[(size_t)eid[i] * 128 + c];
#pragma unroll
            for (int s = 0; s < 9; s++) acc[s] += rv * shs[i * 9 + s];
        }
        __syncthreads();
    }
    size_t b = (size_t)n * TPIN;
    g_A[b + c] = acc[0];
#pragma unroll
    for (int s = 1; s < 4; s++) g_A[b + 128 + c * 3 + (s - 1)] = acc[s];
#pragma unroll
    for (int s = 4; s < 9; s++) g_A[b + 512 + c * 5 + (s - 4)] = acc[s];
}

// ---------------- embed + bias*deg init of g_comb ----------------
__global__ void embed_kernel(const int* __restrict__ an, const float* __restrict__ emb,
                             const float* __restrict__ btp) {
    int i = blockIdx.x * blockDim.x + threadIdx.x;
    if (i < NA * 128) {
        int n = i >> 7, j = i & 127;
        g_comb[i] = (j < 64) ? emb[an[n] * 64 + j]
                             : btp[j - 64] * (float)g_hist[n];
    }
}

// ---------------- split-K GEMM: g_A @ W_tp[:, :64] ----------------
__global__ void agg_gemm_kernel(const float* __restrict__ Wtp) {
    __shared__ float As[32 * 65];
    __shared__ float Bs[32 * 64];
    int tx = threadIdx.x & 15, ty = threadIdx.x >> 4;
    int m0 = blockIdx.x * 64;
    int kb = blockIdx.y * 288;
    float acc[4][4] = {};
    for (int k0 = 0; k0 < 288; k0 += 32) {
#pragma unroll
        for (int i = 0; i < 8; i++) {
            int l = threadIdx.x + i * 256;
            int m = l >> 5, k = l & 31;
            As[k * 65 + m] = g_A[(size_t)(m0 + m) * TPIN + kb + k0 + k];
        }
#pragma unroll
        for (int i = 0; i < 8; i++) {
            int l = threadIdx.x + i * 256;
            int k = l >> 6, n = l & 63;
            Bs[k * 64 + n] = Wtp[(kb + k0 + k) * 128 + n];
        }
        __syncthreads();
#pragma unroll
        for (int k = 0; k < 32; k++) {
            float a[4], b[4];
#pragma unroll
            for (int i = 0; i < 4; i++) a[i] = As[k * 65 + ty * 4 + i];
#pragma unroll
            for (int j = 0; j < 4; j++) b[j] = Bs[k * 64 + tx * 4 + j];
#pragma unroll
            for (int i = 0; i < 4; i++)
#pragma unroll
                for (int j = 0; j < 4; j++) acc[i][j] += a[i] * b[j];
        }
        __syncthreads();
    }
#pragma unroll
    for (int i = 0; i < 4; i++) {
        int m = m0 + ty * 4 + i;
#pragma unroll
        for (int j = 0; j < 4; j++) {
            int n = tx * 4 + j;
            atomicAdd(&g_comb[m * 128 + 64 + n], acc[i][j]);
        }
    }
}

// ---------------- tensor-core split-KV attention partials ----------------
// grid (NA/64, 4 heads, SPLIT), 128 threads (4 warps, warp = 16 query rows)
#define KS_STR 44
#define VS_STR 40
#define PS_STR 76
__global__ __launch_bounds__(128) void attn_part_mma() {
    __shared__ float Ks[64 * KS_STR];
    __shared__ float Vs[64 * VS_STR];
    __shared__ float Ps[64 * PS_STR];
    int tid = threadIdx.x, lane = tid & 31, w = tid >> 5;
    int h = blockIdx.y, sp = blockIdx.z;
    int q0 = blockIdx.x * 64;
    int g = lane >> 2, tg = lane & 3;     // groupID, thread-in-group
    const float sc = 0.17677669529663687f;  // 1/sqrt(32)
    int r0 = q0 + w * 16 + g;             // first query row this thread touches

    // Q fragments (tf32), scaled
    uint32_t Qf[4][4];
#pragma unroll
    for (int kt = 0; kt < 4; kt++) {
        int k0 = kt * 8 + tg;
        Qf[kt][0] = tf32r(g_qkv[(size_t)r0 * 384 + h * 32 + k0] * sc);
        Qf[kt][1] = tf32r(g_qkv[(size_t)(r0 + 8) * 384 + h * 32 + k0] * sc);
        Qf[kt][2] = tf32r(g_qkv[(size_t)r0 * 384 + h * 32 + k0 + 4] * sc);
        Qf[kt][3] = tf32r(g_qkv[(size_t)(r0 + 8) * 384 + h * 32 + k0 + 4] * sc);
    }

    float O[4][4] = {};
    float M0 = -1e30f, M1 = -1e30f, L0 = 0.f, L1 = 0.f;

    for (int t0 = sp * (NA / SPLIT); t0 < (sp + 1) * (NA / SPLIT); t0 += 64) {
        // stage K, V (tf32-rounded)
#pragma unroll
        for (int ii = 0; ii < 4; ii++) {
            int idx = tid + ii * 128;
            int key = idx >> 3, d = (idx & 7) * 4;
            float4 kv = *(const float4*)&g_qkv[(size_t)(t0 + key) * 384 + 128 + h * 32 + d];
            float4 vv = *(const float4*)&g_qkv[(size_t)(t0 + key) * 384 + 256 + h * 32 + d];
            float4 kc, vc;
            kc.x = __uint_as_float(tf32r(kv.x)); kc.y = __uint_as_float(tf32r(kv.y));
            kc.z = __uint_as_float(tf32r(kv.z)); kc.w = __uint_as_float(tf32r(kv.w));
            vc.x = __uint_as_float(tf32r(vv.x)); vc.y = __uint_as_float(tf32r(vv.y));
            vc.z = __uint_as_float(tf32r(vv.z)); vc.w = __uint_as_float(tf32r(vv.w));
            *(float4*)&Ks[key * KS_STR + d] = kc;
            *(float4*)&Vs[key * VS_STR + d] = vc;
        }
        __syncthreads();

        // S = Q @ K^T  (per warp: 16 x 64)
        float S[8][4];
#pragma unroll
        for (int nt = 0; nt < 8; nt++) { S[nt][0] = 0.f; S[nt][1] = 0.f; S[nt][2] = 0.f; S[nt][3] = 0.f; }
#pragma unroll
        for (int nt = 0; nt < 8; nt++)
#pragma unroll
            for (int kt = 0; kt < 4; kt++) {
                uint32_t b0 = __float_as_uint(Ks[(nt * 8 + g) * KS_STR + kt * 8 + tg]);
                uint32_t b1 = __float_as_uint(Ks[(nt * 8 + g) * KS_STR + kt * 8 + tg + 4]);
                mma_tf32(S[nt], Qf[kt], b0, b1);
            }

        // online softmax (rows r0 -> c0/c1, r0+8 -> c2/c3)
        float rm0 = -1e30f, rm1 = -1e30f;
#pragma unroll
        for (int nt = 0; nt < 8; nt++) {
            rm0 = fmaxf(rm0, fmaxf(S[nt][0], S[nt][1]));
            rm1 = fmaxf(rm1, fmaxf(S[nt][2], S[nt][3]));
        }
        rm0 = fmaxf(rm0, __shfl_xor_sync(0xffffffffu, rm0, 1));
        rm0 = fmaxf(rm0, __shfl_xor_sync(0xffffffffu, rm0, 2));
        rm1 = fmaxf(rm1, __shfl_xor_sync(0xffffffffu, rm1, 1));
        rm1 = fmaxf(rm1, __shfl_xor_sync(0xffffffffu, rm1, 2));
        float Mn0 = fmaxf(M0, rm0), Mn1 = fmaxf(M1, rm1);
        float sc0 = __expf(M0 - Mn0), sc1 = __expf(M1 - Mn1);
        M0 = Mn0; M1 = Mn1;
        float ps0 = 0.f, ps1 = 0.f;
#pragma unroll
        for (int nt = 0; nt < 8; nt++) {
            S[nt][0] = __expf(S[nt][0] - Mn0); ps0 += S[nt][0];
            S[nt][1] = __expf(S[nt][1] - Mn0); ps0 += S[nt][1];
            S[nt][2] = __expf(S[nt][2] - Mn1); ps1 += S[nt][2];
            S[nt][3] = __expf(S[nt][3] - Mn1); ps1 += S[nt][3];
        }
        ps0 += __shfl_xor_sync(0xffffffffu, ps0, 1);
        ps0 += __shfl_xor_sync(0xffffffffu, ps0, 2);
        ps1 += __shfl_xor_sync(0xffffffffu, ps1, 1);
        ps1 += __shfl_xor_sync(0xffffffffu, ps1, 2);
        L0 = L0 * sc0 + ps0;
        L1 = L1 * sc1 + ps1;
#pragma unroll
        for (int nt2 = 0; nt2 < 4; nt2++) {
            O[nt2][0] *= sc0; O[nt2][1] *= sc0;
            O[nt2][2] *= sc1; O[nt2][3] *= sc1;
        }

        // store P (tf32-rounded) to smem
        int pr = w * 16 + g;
#pragma unroll
        for (int nt = 0; nt < 8; nt++) {
            Ps[pr * PS_STR + nt * 8 + 2 * tg]           = __uint_as_float(tf32r(S[nt][0]));
            Ps[pr * PS_STR + nt * 8 + 2 * tg + 1]       = __uint_as_float(tf32r(S[nt][1]));
            Ps[(pr + 8) * PS_STR + nt * 8 + 2 * tg]     = __uint_as_float(tf32r(S[nt][2]));
            Ps[(pr + 8) * PS_STR + nt * 8 + 2 * tg + 1] = __uint_as_float(tf32r(S[nt][3]));
        }
        __syncwarp();

        // O += P @ V  (per warp: 16 x 32)
#pragma unroll
        for (int kt2 = 0; kt2 < 8; kt2++) {
            uint32_t A[4];
            A[0] = __float_as_uint(Ps[pr * PS_STR + kt2 * 8 + tg]);
            A[1] = __float_as_uint(Ps[(pr + 8) * PS_STR + kt2 * 8 + tg]);
            A[2] = __float_as_uint(Ps[pr * PS_STR + kt2 * 8 + tg + 4]);
            A[3] = __float_as_uint(Ps[(pr + 8) * PS_STR + kt2 * 8 + tg + 4]);
#pragma unroll
            for (int nt2 = 0; nt2 < 4; nt2++) {
                uint32_t b0 = __float_as_uint(Vs[(kt2 * 8 + tg) * VS_STR + nt2 * 8 + g]);
                uint32_t b1 = __float_as_uint(Vs[(kt2 * 8 + tg + 4) * VS_STR + nt2 * 8 + g]);
                mma_tf32(O[nt2], A, b0, b1);
            }
        }
        __syncthreads();
    }

    // write unnormalized partials + (M, L)
    size_t base = (size_t)sp * NA;
#pragma unroll
    for (int nt2 = 0; nt2 < 4; nt2++) {
        int col = h * 32 + nt2 * 8 + 2 * tg;
        g_pO[(base + r0) * 128 + col]           = O[nt2][0];
        g_pO[(base + r0) * 128 + col + 1]       = O[nt2][1];
        g_pO[(base + r0 + 8) * 128 + col]       = O[nt2][2];
        g_pO[(base + r0 + 8) * 128 + col + 1]   = O[nt2][3];
    }
    if (tg == 0) {
        g_pml[((base + r0) * 4 + h) * 2 + 0]     = M0;
        g_pml[((base + r0) * 4 + h) * 2 + 1]     = L0;
        g_pml[((base + r0 + 8) * 4 + h) * 2 + 0] = M1;
        g_pml[((base + r0 + 8) * 4 + h) * 2 + 1] = L1;
    }
}

// ---------------- combine split-KV partials ----------------
__global__ void attn_combine_kernel() {
    int i = blockIdx.x * blockDim.x + threadIdx.x;
    if (i >= NA * 128) return;
    int qi = i >> 7, hd = i & 127, h = hd >> 5;
    float m[SPLIT], l[SPLIT];
    float M = -1e30f;
#pragma unroll
    for (int s = 0; s < SPLIT; s++) {
        size_t base = (size_t)s * NA + qi;
        m[s] = g_pml[(base * 4 + h) * 2 + 0];
        l[s] = g_pml[(base * 4 + h) * 2 + 1];
        M = fmaxf(M, m[s]);
    }
    float L = 0.f, O = 0.f;
#pragma unroll
    for (int s = 0; s < SPLIT; s++) {
        float w = __expf(m[s] - M);
        L += l[s] * w;
        O += g_pO[((size_t)s * NA + qi) * 128 + hd] * w;
    }
    g_att[i] = O / L;
}

// ---------------- fused: t1 = att@Wao+bao; g = sig(upd@Wg+bg); mix ---------
__global__ void gemm_dual_kernel(const float* __restrict__ Wao, const float* __restrict__ bao,
                                 const float* __restrict__ Wg,  const float* __restrict__ bg) {
    __shared__ float As1[32 * 65];
    __shared__ float As2[32 * 65];
    __shared__ float Bs1[32 * 64];
    __shared__ float Bs2[32 * 64];
    int tx = threadIdx.x & 15, ty = threadIdx.x >> 4;
    int m0 = blockIdx.x * 64, n0 = blockIdx.y * 64;
    float acc1[4][4] = {}, acc2[4][4] = {};
    for (int k0 = 0; k0 < 128; k0 += 32) {
#pragma unroll
        for (int i = 0; i < 8; i++) {
            int l = threadIdx.x + i * 256;
            int m = l >> 5, k = l & 31;
            As1[k * 65 + m] = g_att[(size_t)(m0 + m) * 128 + k0 + k];
            As2[k * 65 + m] = g_upd[(size_t)(m0 + m) * 128 + k0 + k];
        }
#pragma unroll
        for (int i = 0; i < 8; i++) {
            int l = threadIdx.x + i * 256;
            int k = l >> 6, n = l & 63;
            Bs1[k * 64 + n] = Wao[(k0 + k) * 128 + n0 + n];
            Bs2[k * 64 + n] = Wg[(k0 + k) * 128 + n0 + n];
        }
        __syncthreads();
#pragma unroll
        for (int k = 0; k < 32; k++) {
            float a1[4], a2[4], b1v[4], b2v[4];
#pragma unroll
            for (int i = 0; i < 4; i++) { a1[i] = As1[k * 65 + ty * 4 + i]; a2[i] = As2[k * 65 + ty * 4 + i]; }
#pragma unroll
            for (int j = 0; j < 4; j++) { b1v[j] = Bs1[k * 64 + tx * 4 + j]; b2v[j] = Bs2[k * 64 + tx * 4 + j]; }
#pragma unroll
            for (int i = 0; i < 4; i++)
#pragma unroll
                for (int j = 0; j < 4; j++) {
                    acc1[i][j] += a1[i] * b1v[j];
                    acc2[i][j] += a2[i] * b2v[j];
                }
        }
        __syncthreads();
    }
#pragma unroll
    for (int i = 0; i < 4; i++) {
        int m = m0 + ty * 4 + i;
#pragma unroll
        for (int j = 0; j < 4; j++) {
            int n = n0 + tx * 4 + j;
            float t1 = acc1[i][j] + bao[n];
            float gg = 1.f / (1.f + __expf(-(acc2[i][j] + bg[n])));
            float u = g_upd[(size_t)m * 128 + n];
            g_mix[(size_t)m * 128 + n] = gg * t1 + (1.f - gg) * u;
        }
    }
}

// ---------------- launch ----------------
extern "C" void kernel_launch(void* const* d_in, const int* in_sizes, int n_in,
                              void* d_out, int out_size) {
    const int*   an    = (const int*)d_in[0];
    const int*   ei    = (const int*)d_in[2];
    const float* ev    = (const float*)d_in[3];
    const float* el    = (const float*)d_in[4];
    const float* emb   = (const float*)d_in[5];
    const float* W_r1  = (const float*)d_in[6];  const float* b_r1 = (const float*)d_in[7];
    const float* W_r2  = (const float*)d_in[8];  const float* b_r2 = (const float*)d_in[9];
    const float* W_tp  = (const float*)d_in[10]; const float* b_tp = (const float*)d_in[11];
    const float* W_m1  = (const float*)d_in[12]; const float* b_m1 = (const float*)d_in[13];
    const float* W_m2  = (const float*)d_in[14]; const float* b_m2 = (const float*)d_in[15];
    const float* W_qkv = (const float*)d_in[16]; const float* b_qkv= (const float*)d_in[17];
    const float* W_ao  = (const float*)d_in[18]; const float* b_ao = (const float*)d_in[19];
    const float* W_g   = (const float*)d_in[20]; const float* b_g  = (const float*)d_in[21];
    const float* W_o   = (const float*)d_in[22]; const float* b_o  = (const float*)d_in[23];
    float* out = (float*)d_out;

    float *p_comb, *p_hid, *p_upd, *p_qkv, *p_mix;
    cudaGetSymbolAddress((void**)&p_comb, g_comb);
    cudaGetSymbolAddress((void**)&p_hid,  g_hid);
    cudaGetSymbolAddress((void**)&p_upd,  g_upd);
    cudaGetSymbolAddress((void**)&p_qkv,  g_qkv);
    cudaGetSymbolAddress((void**)&p_mix,  g_mix);

    zero_hist_kernel<<<16, 256>>>();
    hist_kernel<<<512, 256>>>(ei);
    edge_fused_kernel<<<512, 256>>>(ev, el, W_r1, b_r1, W_r2, b_r2);
    scan_kernel<<<1, 1024>>>();
    scatter_kernel<<<512, 256>>>(ei);
    aggregate_kernel<<<NA, 128>>>();
    embed_kernel<<<NA * 128 / 256, 256>>>(an, emb, b_tp);
    agg_gemm_kernel<<<dim3(NA / 64, 4), 256>>>(W_tp);
    gemm_kernel<<<dim3(NA / 64, 2), 256>>>(p_comb, W_m1, b_m1, p_hid, NA, 128, 128, 1);
    gemm_kernel<<<dim3(NA / 64, 2), 256>>>(p_hid, W_m2, b_m2, p_upd, NA, 128, 128, 0);
    gemm_kernel<<<dim3(NA / 64, 6), 256>>>(p_upd, W_qkv, b_qkv, p_qkv, NA, 384, 128, 0);
    attn_part_mma<<<dim3(NA / 64, 4, SPLIT), 128>>>();
    attn_combine_kernel<<<NA * 128 / 256, 256>>>();
    gemm_dual_kernel<<<dim3(NA / 64, 2), 256>>>(W_ao, b_ao, W_g, b_g);
    gemm_kernel<<<dim3(NA / 64, 2), 256>>>(p_mix, W_o, b_o, out, NA, 128, 128, 0);
}